// round 17
// baseline (speedup 1.0000x reference)
#include <cuda_runtime.h>
#include <cuda_bf16.h>
#include <cuda_fp16.h>
#include <cstdint>

#define NTOK 8192
#define DIM  128
#define CIN  256
#define HWD  1024
#define LOG2E 1.4426950408889634f
#define KVT32 256            // 8192 / 32 key-tiles
#define NFLASH 128           // flash CTAs (bids 0..127)
#define NGATE 512            // gate chunks (bids 128..639)

// ---------------- device workspaces ----------------
__device__ __align__(256) __nv_bfloat16 g_xb[NTOK * CIN];
__device__ __align__(256) __nv_bfloat16 g_Wb[3 * DIM * CIN];   // W^T bf16 [sel][n][k]
__device__ __align__(256) __nv_bfloat16 g_Q[NTOK * DIM];
__device__ __align__(256) __nv_bfloat16 g_K[NTOK * DIM];
__device__ __align__(256) __half        g_V[NTOK * DIM];       // V in f16 (PV mma f16 acc)
__device__ __align__(256) float g_O[NTOK * DIM];               // normalized attention out
__device__ float g_logits[8 * HWD];
__device__ float g_sp[8 * HWD];

// ---------------- PTX helpers ----------------
__device__ __forceinline__ uint32_t smem_u32(const void* p) {
    return (uint32_t)__cvta_generic_to_shared(p);
}
__device__ __forceinline__ void ldsm_x4(uint32_t& r0, uint32_t& r1, uint32_t& r2, uint32_t& r3, uint32_t a) {
    asm volatile("ldmatrix.sync.aligned.m8n8.x4.shared.b16 {%0,%1,%2,%3},[%4];"
                 : "=r"(r0), "=r"(r1), "=r"(r2), "=r"(r3) : "r"(a));
}
__device__ __forceinline__ void ldsm_x4_t(uint32_t& r0, uint32_t& r1, uint32_t& r2, uint32_t& r3, uint32_t a) {
    asm volatile("ldmatrix.sync.aligned.m8n8.x4.trans.shared.b16 {%0,%1,%2,%3},[%4];"
                 : "=r"(r0), "=r"(r1), "=r"(r2), "=r"(r3) : "r"(a));
}
__device__ __forceinline__ void mma16816(float c[4], const uint32_t a[4], uint32_t b0, uint32_t b1) {
    asm volatile("mma.sync.aligned.m16n8k16.row.col.f32.bf16.bf16.f32 "
                 "{%0,%1,%2,%3},{%4,%5,%6,%7},{%8,%9},{%0,%1,%2,%3};"
                 : "+f"(c[0]), "+f"(c[1]), "+f"(c[2]), "+f"(c[3])
                 : "r"(a[0]), "r"(a[1]), "r"(a[2]), "r"(a[3]), "r"(b0), "r"(b1));
}
__device__ __forceinline__ void mma16816h(uint32_t c[2], const uint32_t a[4], uint32_t b0, uint32_t b1) {
    asm volatile("mma.sync.aligned.m16n8k16.row.col.f16.f16.f16.f16 "
                 "{%0,%1},{%2,%3,%4,%5},{%6,%7},{%0,%1};"
                 : "+r"(c[0]), "+r"(c[1])
                 : "r"(a[0]), "r"(a[1]), "r"(a[2]), "r"(a[3]), "r"(b0), "r"(b1));
}
__device__ __forceinline__ float ex2f(float x) {
    float r; asm("ex2.approx.f32 %0,%1;" : "=f"(r) : "f"(x)); return r;
}
__device__ __forceinline__ uint32_t packbf(float lo, float hi) {
    uint32_t r; asm("cvt.rn.bf16x2.f32 %0,%1,%2;" : "=r"(r) : "f"(hi), "f"(lo)); return r;
}
__device__ __forceinline__ uint32_t packhf(float lo, float hi) {
    uint32_t r; asm("cvt.rn.f16x2.f32 %0,%1,%2;" : "=r"(r) : "f"(hi), "f"(lo)); return r;
}
__device__ __forceinline__ uint32_t mulh2(uint32_t a, uint32_t b) {
    uint32_t r; asm("mul.f16x2 %0,%1,%2;" : "=r"(r) : "r"(a), "r"(b)); return r;
}
__device__ __forceinline__ void ffma2(unsigned long long& acc, unsigned long long a, unsigned long long b) {
    asm("fma.rn.f32x2 %0, %1, %2, %0;" : "+l"(acc) : "l"(a), "l"(b));
}
__device__ __forceinline__ unsigned long long bcast2(float v) {
    unsigned long long r; asm("mov.b64 %0, {%1, %1};" : "=l"(r) : "f"(v)); return r;
}
__device__ __forceinline__ float2 unpack2(unsigned long long v) {
    float2 r; asm("mov.b64 {%0, %1}, %2;" : "=f"(r.x), "=f"(r.y) : "l"(v)); return r;
}

// ==================== convert: x -> bf16, W{t,p,a} -> bf16 transposed ====================
__global__ void convert_kernel(const float* __restrict__ x,
                               const float* __restrict__ Wt,
                               const float* __restrict__ Wp,
                               const float* __restrict__ Wa) {
    const int bx = blockIdx.x, tid = threadIdx.x;
    if (bx < 2048) {
        int gid = bx * 256 + tid;
        float4 v = *(const float4*)(x + (size_t)gid * 4);
        uint2 p;
        p.x = packbf(v.x, v.y);
        p.y = packbf(v.z, v.w);
        *(uint2*)(g_xb + (size_t)gid * 4) = p;
    } else {
        int i = (bx - 2048) * 256 + tid;
        int sel = i >> 15;
        int k = i & 255;
        int n = (i >> 8) & 127;
        const float* W = (sel == 0) ? Wt : (sel == 1) ? Wp : Wa;
        g_Wb[sel * 32768 + n * 256 + k] = __float2bfloat16(W[k * 128 + n]);
    }
}

// ==================== proj via tensor cores (V written as f16) ====================
#define PROWP 264
#define PROJ_SMEM ((64 + 128) * PROWP * 2)

__global__ void __launch_bounds__(128) proj_mma_kernel(const float* __restrict__ bt,
                                                       const float* __restrict__ bp,
                                                       const float* __restrict__ ba) {
    extern __shared__ __align__(16) __nv_bfloat16 psh[];
    __nv_bfloat16* sA = psh;
    __nv_bfloat16* sB = psh + 64 * PROWP;
    __shared__ float sbias[128];
    const int sel = blockIdx.y;
    const float* bias = (sel == 0) ? bt : (sel == 1) ? bp : ba;
    const __nv_bfloat16* A = g_xb + (size_t)blockIdx.x * 64 * CIN;
    const __nv_bfloat16* B = g_Wb + (size_t)sel * DIM * CIN;
    const int tid = threadIdx.x, lane = tid & 31, warp = tid >> 5;

    sbias[tid] = bias[tid];

#pragma unroll
    for (int p = 0; p < 16; ++p) {
        int idx = p * 128 + tid;
        int row = idx >> 5, cc = idx & 31;
        uint32_t d = smem_u32(sA + row * PROWP + cc * 8);
        asm volatile("cp.async.cg.shared.global [%0],[%1],16;" :: "r"(d), "l"(A + row * CIN + cc * 8) : "memory");
    }
#pragma unroll
    for (int p = 0; p < 32; ++p) {
        int idx = p * 128 + tid;
        int row = idx >> 5, cc = idx & 31;
        uint32_t d = smem_u32(sB + row * PROWP + cc * 8);
        asm volatile("cp.async.cg.shared.global [%0],[%1],16;" :: "r"(d), "l"(B + row * CIN + cc * 8) : "memory");
    }
    asm volatile("cp.async.commit_group;" ::: "memory");
    asm volatile("cp.async.wait_group 0;" ::: "memory");
    __syncthreads();

    uint32_t af[16][4];
    {
        int arow = warp * 16 + (lane & 7) + ((lane & 8) ? 8 : 0);
        int acb = (lane & 16) ? 8 : 0;
#pragma unroll
        for (int kk = 0; kk < 16; ++kk)
            ldsm_x4(af[kk][0], af[kk][1], af[kk][2], af[kk][3],
                    smem_u32(sA + arow * PROWP + kk * 16 + acb));
    }
    float acc[16][4];
#pragma unroll
    for (int n = 0; n < 16; ++n) { acc[n][0] = acc[n][1] = acc[n][2] = acc[n][3] = 0.f; }

    const int brow = (lane & 7) + ((lane & 16) ? 8 : 0);
    const int bc8  = (lane & 8) ? 8 : 0;
#pragma unroll
    for (int kk = 0; kk < 16; ++kk) {
#pragma unroll
        for (int np = 0; np < 8; ++np) {
            uint32_t b0, b1, b2, b3;
            ldsm_x4(b0, b1, b2, b3, smem_u32(sB + (np * 16 + brow) * PROWP + kk * 16 + bc8));
            mma16816(acc[2 * np],     af[kk], b0, b1);
            mma16816(acc[2 * np + 1], af[kk], b2, b3);
        }
    }

    int r0 = blockIdx.x * 64 + warp * 16 + (lane >> 2);
    int c0 = 2 * (lane & 3);
#pragma unroll
    for (int n = 0; n < 16; ++n) {
        int c = n * 8 + c0;
        float b0v = sbias[c], b1v = sbias[c + 1];
        float v00 = acc[n][0] + b0v, v01 = acc[n][1] + b1v;
        float v10 = acc[n][2] + b0v, v11 = acc[n][3] + b1v;
        if (sel == 2) {
            *(uint32_t*)&g_V[(size_t)r0 * DIM + c]       = packhf(v00, v01);
            *(uint32_t*)&g_V[(size_t)(r0 + 8) * DIM + c] = packhf(v10, v11);
        } else {
            __nv_bfloat16* dst = (sel == 0) ? g_Q : g_K;
            *(uint32_t*)&dst[(size_t)r0 * DIM + c]       = packbf(v00, v01);
            *(uint32_t*)&dst[(size_t)(r0 + 8) * DIM + c] = packbf(v10, v11);
        }
    }
}

// ==================== gate body (FFMA2, depth-8 pipelined streaming) ====================
__device__ void gate_body(const float* __restrict__ x, const float* __restrict__ Wd,
                          int chunk, float* xs) {
    const int tid = threadIdx.x;
    const int k0 = chunk * 512;
    for (int i = tid; i < 4096; i += 128) {
        int kl = i & 511, b = i >> 9;
        xs[kl * 8 + b] = x[(size_t)b * 262144 + k0 + kl];
    }
    __syncthreads();

    unsigned long long acc[8][4];
#pragma unroll
    for (int b = 0; b < 8; ++b)
#pragma unroll
        for (int c = 0; c < 4; ++c) acc[b][c] = 0ull;

    const int cA = tid * 4, cB = 512 + tid * 4;

    longlong2 pw[4][2];
    {
        const float* wr = Wd + (size_t)k0 * 1024;
#pragma unroll
        for (int r = 0; r < 4; ++r) {
            pw[r][0] = __ldcs((const longlong2*)(wr + (size_t)r * 1024 + cA));
            pw[r][1] = __ldcs((const longlong2*)(wr + (size_t)r * 1024 + cB));
        }
    }

    for (int kl = 0; kl < 512; kl += 4) {
        longlong2 cur[4][2];
#pragma unroll
        for (int r = 0; r < 4; ++r) { cur[r][0] = pw[r][0]; cur[r][1] = pw[r][1]; }
        if (kl + 4 < 512) {
            const float* wr = Wd + (size_t)(k0 + kl + 4) * 1024;
#pragma unroll
            for (int r = 0; r < 4; ++r) {
                pw[r][0] = __ldcs((const longlong2*)(wr + (size_t)r * 1024 + cA));
                pw[r][1] = __ldcs((const longlong2*)(wr + (size_t)r * 1024 + cB));
            }
        }
#pragma unroll
        for (int r = 0; r < 4; ++r) {
            unsigned long long w0 = (unsigned long long)cur[r][0].x, w1 = (unsigned long long)cur[r][0].y;
            unsigned long long w2 = (unsigned long long)cur[r][1].x, w3 = (unsigned long long)cur[r][1].y;
            float4 xa = *(const float4*)&xs[(kl + r) * 8];
            float4 xb = *(const float4*)&xs[(kl + r) * 8 + 4];
            unsigned long long xp;
            xp = bcast2(xa.x); ffma2(acc[0][0], w0, xp); ffma2(acc[0][1], w1, xp); ffma2(acc[0][2], w2, xp); ffma2(acc[0][3], w3, xp);
            xp = bcast2(xa.y); ffma2(acc[1][0], w0, xp); ffma2(acc[1][1], w1, xp); ffma2(acc[1][2], w2, xp); ffma2(acc[1][3], w3, xp);
            xp = bcast2(xa.z); ffma2(acc[2][0], w0, xp); ffma2(acc[2][1], w1, xp); ffma2(acc[2][2], w2, xp); ffma2(acc[2][3], w3, xp);
            xp = bcast2(xa.w); ffma2(acc[3][0], w0, xp); ffma2(acc[3][1], w1, xp); ffma2(acc[3][2], w2, xp); ffma2(acc[3][3], w3, xp);
            xp = bcast2(xb.x); ffma2(acc[4][0], w0, xp); ffma2(acc[4][1], w1, xp); ffma2(acc[4][2], w2, xp); ffma2(acc[4][3], w3, xp);
            xp = bcast2(xb.y); ffma2(acc[5][0], w0, xp); ffma2(acc[5][1], w1, xp); ffma2(acc[5][2], w2, xp); ffma2(acc[5][3], w3, xp);
            xp = bcast2(xb.z); ffma2(acc[6][0], w0, xp); ffma2(acc[6][1], w1, xp); ffma2(acc[6][2], w2, xp); ffma2(acc[6][3], w3, xp);
            xp = bcast2(xb.w); ffma2(acc[7][0], w0, xp); ffma2(acc[7][1], w1, xp); ffma2(acc[7][2], w2, xp); ffma2(acc[7][3], w3, xp);
        }
    }
#pragma unroll
    for (int b = 0; b < 8; ++b) {
        float2 v0 = unpack2(acc[b][0]);
        float2 v1 = unpack2(acc[b][1]);
        float2 v2 = unpack2(acc[b][2]);
        float2 v3 = unpack2(acc[b][3]);
        float* p = g_logits + b * HWD;
        atomicAdd(p + cA + 0, v0.x); atomicAdd(p + cA + 1, v0.y);
        atomicAdd(p + cA + 2, v1.x); atomicAdd(p + cA + 3, v1.y);
        atomicAdd(p + cB + 0, v2.x); atomicAdd(p + cB + 1, v2.y);
        atomicAdd(p + cB + 2, v3.x); atomicAdd(p + cB + 3, v3.y);
    }
}

// ==================== fat kernel: 1 flash + 2 gate per SM (3 CTAs/SM) ====================
#define ROWP 136
#define QTILE (64 * ROWP)        // 8704 elems
#define KVTILE (32 * ROWP)       // 4352 elems
#define FLASH_SMEM ((QTILE + 4 * KVTILE) * 2)   // 52224 B

__device__ __forceinline__ void load_q(__nv_bfloat16* dst, const __nv_bfloat16* src, int tid) {
#pragma unroll
    for (int it = 0; it < 8; ++it) {
        int c = tid + it * 128;
        int row = c >> 4, cc = c & 15;
        uint32_t d = smem_u32(dst + row * ROWP + cc * 8);
        asm volatile("cp.async.cg.shared.global [%0],[%1],16;" :: "r"(d), "l"(src + row * DIM + cc * 8) : "memory");
    }
}
// 32x128 16-bit tile (8 KB)
__device__ __forceinline__ void load_kv(void* dst, const void* src, int tid) {
#pragma unroll
    for (int it = 0; it < 4; ++it) {
        int c = tid + it * 128;
        int row = c >> 4, cc = c & 15;
        uint32_t d = smem_u32((const char*)dst + (row * ROWP + cc * 8) * 2);
        const char* s = (const char*)src + (row * DIM + cc * 8) * 2;
        asm volatile("cp.async.cg.shared.global [%0],[%1],16;" :: "r"(d), "l"(s) : "memory");
    }
}

__global__ void __launch_bounds__(128, 3) fat_kernel(const float* __restrict__ x,
                                                     const float* __restrict__ Wd) {
    extern __shared__ __align__(16) __nv_bfloat16 sh[];
    const int bid = blockIdx.x;

    if (bid >= NFLASH) {
        gate_body(x, Wd, bid - NFLASH, (float*)sh);
        return;
    }
    // ---- flash: full 8192-key pass for 64 queries, Bc=32 ----
    __nv_bfloat16* sQ = sh;
    __nv_bfloat16* sK = sh + QTILE;                 // 2 buffers
    __half*        sV = (__half*)(sh + QTILE + 2 * KVTILE);  // 2 buffers
    const int tid = threadIdx.x, lane = tid & 31, warp = tid >> 5;
    const int q0 = bid * 64;

    load_q(sQ, g_Q + (size_t)q0 * DIM, tid);
    asm volatile("cp.async.commit_group;" ::: "memory");
    load_kv(sK, g_K, tid);
    load_kv(sV, g_V, tid);
    asm volatile("cp.async.commit_group;" ::: "memory");
    asm volatile("cp.async.wait_group 1;" ::: "memory");   // Q ready
    __syncthreads();

    uint32_t qf[8][4];
    {
        int row = warp * 16 + (lane & 7) + ((lane & 8) ? 8 : 0);
        int cb = (lane & 16) ? 8 : 0;
#pragma unroll
        for (int kk = 0; kk < 8; ++kk)
            ldsm_x4(qf[kk][0], qf[kk][1], qf[kk][2], qf[kk][3],
                    smem_u32(sQ + row * ROWP + kk * 16 + cb));
    }

    uint32_t oacc[16][2];      // f16x2 accumulators
#pragma unroll
    for (int n = 0; n < 16; ++n) { oacc[n][0] = 0u; oacc[n][1] = 0u; }
    float m0 = -1e30f, m1 = -1e30f, l0 = 0.f, l1 = 0.f;

    const int krow = (lane & 7) + ((lane & 16) ? 8 : 0);
    const int kc8  = (lane & 8) ? 8 : 0;
    const int vrow = (lane & 7) + ((lane & 8) ? 8 : 0);
    const int vc8  = (lane & 16) ? 8 : 0;

    for (int t = 0; t < KVT32; ++t) {
        const int buf = t & 1;
        if (t < KVT32 - 1) {
            load_kv(sK + (1 - buf) * KVTILE, g_K + (size_t)(t + 1) * 32 * DIM, tid);
            load_kv(sV + (1 - buf) * KVTILE, g_V + (size_t)(t + 1) * 32 * DIM, tid);
        }
        asm volatile("cp.async.commit_group;" ::: "memory");
        asm volatile("cp.async.wait_group 1;" ::: "memory");   // tile t ready
        __syncthreads();
        const __nv_bfloat16* kb = sK + buf * KVTILE;
        const __half* vb = sV + buf * KVTILE;

        // S = Q K^T : 16 rows x 32 keys per warp
        float sacc[4][4];
#pragma unroll
        for (int n = 0; n < 4; ++n) { sacc[n][0] = sacc[n][1] = sacc[n][2] = sacc[n][3] = 0.f; }
#pragma unroll
        for (int kk = 0; kk < 8; ++kk) {
#pragma unroll
            for (int np = 0; np < 2; ++np) {
                uint32_t b0, b1, b2, b3;
                ldsm_x4(b0, b1, b2, b3, smem_u32(kb + (np * 16 + krow) * ROWP + kk * 16 + kc8));
                mma16816(sacc[2 * np],     qf[kk], b0, b1);
                mma16816(sacc[2 * np + 1], qf[kk], b2, b3);
            }
        }

        // online softmax
        float mx0 = -1e30f, mx1 = -1e30f;
#pragma unroll
        for (int n = 0; n < 4; ++n) {
            mx0 = fmaxf(mx0, fmaxf(sacc[n][0], sacc[n][1]));
            mx1 = fmaxf(mx1, fmaxf(sacc[n][2], sacc[n][3]));
        }
        mx0 = fmaxf(mx0, __shfl_xor_sync(0xffffffffu, mx0, 1));
        mx0 = fmaxf(mx0, __shfl_xor_sync(0xffffffffu, mx0, 2));
        mx1 = fmaxf(mx1, __shfl_xor_sync(0xffffffffu, mx1, 1));
        mx1 = fmaxf(mx1, __shfl_xor_sync(0xffffffffu, mx1, 2));
        float mn0 = fmaxf(m0, mx0), mn1 = fmaxf(m1, mx1);
        float sc0 = ex2f((m0 - mn0) * LOG2E), sc1 = ex2f((m1 - mn1) * LOG2E);
        float rs0 = 0.f, rs1 = 0.f;
#pragma unroll
        for (int n = 0; n < 4; ++n) {
            sacc[n][0] = ex2f((sacc[n][0] - mn0) * LOG2E);
            sacc[n][1] = ex2f((sacc[n][1] - mn0) * LOG2E);
            sacc[n][2] = ex2f((sacc[n][2] - mn1) * LOG2E);
            sacc[n][3] = ex2f((sacc[n][3] - mn1) * LOG2E);
            rs0 += sacc[n][0] + sacc[n][1];
            rs1 += sacc[n][2] + sacc[n][3];
        }
        rs0 += __shfl_xor_sync(0xffffffffu, rs0, 1);
        rs0 += __shfl_xor_sync(0xffffffffu, rs0, 2);
        rs1 += __shfl_xor_sync(0xffffffffu, rs1, 1);
        rs1 += __shfl_xor_sync(0xffffffffu, rs1, 2);
        l0 = l0 * sc0 + rs0; l1 = l1 * sc1 + rs1;
        m0 = mn0; m1 = mn1;

        uint32_t s0h = packhf(sc0, sc0), s1h = packhf(sc1, sc1);
#pragma unroll
        for (int n = 0; n < 16; ++n) {
            oacc[n][0] = mulh2(oacc[n][0], s0h);
            oacc[n][1] = mulh2(oacc[n][1], s1h);
        }

        // P -> f16 A frags (2 k-chunks of 16)
        uint32_t pf[2][4];
#pragma unroll
        for (int i = 0; i < 2; ++i) {
            pf[i][0] = packhf(sacc[2 * i][0],     sacc[2 * i][1]);
            pf[i][1] = packhf(sacc[2 * i][2],     sacc[2 * i][3]);
            pf[i][2] = packhf(sacc[2 * i + 1][0], sacc[2 * i + 1][1]);
            pf[i][3] = packhf(sacc[2 * i + 1][2], sacc[2 * i + 1][3]);
        }

        // O += P V (f16 acc)
#pragma unroll
        for (int i = 0; i < 2; ++i) {
#pragma unroll
            for (int np = 0; np < 8; ++np) {
                uint32_t b0, b1, b2, b3;
                ldsm_x4_t(b0, b1, b2, b3, smem_u32(vb + (i * 16 + vrow) * ROWP + np * 16 + vc8));
                mma16816h(oacc[2 * np],     pf[i], b0, b1);
                mma16816h(oacc[2 * np + 1], pf[i], b2, b3);
            }
        }
        __syncthreads();
    }

    float inv0 = 1.f / l0, inv1 = 1.f / l1;
    int row0 = q0 + warp * 16 + (lane >> 2);
    int c0 = 2 * (lane & 3);
#pragma unroll
    for (int n = 0; n < 16; ++n) {
        int c = n * 8 + c0;
        float2 v0 = __half22float2(*reinterpret_cast<__half2*>(&oacc[n][0]));
        float2 v1 = __half22float2(*reinterpret_cast<__half2*>(&oacc[n][1]));
        *(float2*)&g_O[(size_t)row0 * DIM + c]       = make_float2(v0.x * inv0, v0.y * inv0);
        *(float2*)&g_O[(size_t)(row0 + 8) * DIM + c] = make_float2(v1.x * inv1, v1.y * inv1);
    }
}

// ==================== small kernels ====================
__global__ void zero_logits_kernel() {
    g_logits[blockIdx.x * 1024 + threadIdx.x] = 0.f;
}

__global__ void gate_softmax(const float* __restrict__ bd) {
    __shared__ float red[32];
    __shared__ float bc;
    const int b = blockIdx.x, j = threadIdx.x;
    const int lane = j & 31, w = j >> 5;
    float v = g_logits[b * HWD + j] + bd[j];
    float m = v;
#pragma unroll
    for (int o = 16; o; o >>= 1) m = fmaxf(m, __shfl_xor_sync(0xffffffffu, m, o));
    if (lane == 0) red[w] = m;
    __syncthreads();
    if (j < 32) {
        float t = red[j];
#pragma unroll
        for (int o = 16; o; o >>= 1) t = fmaxf(t, __shfl_xor_sync(0xffffffffu, t, o));
        if (j == 0) bc = t;
    }
    __syncthreads();
    float e = expf(v - bc);
    float s = e;
#pragma unroll
    for (int o = 16; o; o >>= 1) s += __shfl_xor_sync(0xffffffffu, s, o);
    if (lane == 0) red[w] = s;
    __syncthreads();
    if (j < 32) {
        float t = red[j];
#pragma unroll
        for (int o = 16; o; o >>= 1) t += __shfl_xor_sync(0xffffffffu, t, o);
        if (j == 0) bc = t;
    }
    __syncthreads();
    g_sp[b * HWD + j] = e / bc;
}

// ==================== epilogue: (O @ W_mask) * sp + x ====================
__global__ void epilogue_kernel(const float* __restrict__ x, const float* __restrict__ Wm,
                                float* __restrict__ out) {
    __shared__ float4 sO[32 * 32];
    __shared__ float ssp[32];
    const int tid = threadIdx.x;
    const int t0 = blockIdx.x * 32;
    if (tid < 32) ssp[tid] = g_sp[t0 + tid];
    const float4* og = (const float4*)(g_O + (size_t)t0 * DIM);
    for (int i = tid; i < 1024; i += 256) sO[i] = og[i];
    __syncthreads();
    const int j = tid;
    float acc[32];
#pragma unroll
    for (int t = 0; t < 32; ++t) acc[t] = 0.f;
    for (int k4 = 0; k4 < 32; ++k4) {
        float w0 = Wm[(k4 * 4 + 0) * CIN + j];
        float w1 = Wm[(k4 * 4 + 1) * CIN + j];
        float w2 = Wm[(k4 * 4 + 2) * CIN + j];
        float w3 = Wm[(k4 * 4 + 3) * CIN + j];
#pragma unroll
        for (int t = 0; t < 32; ++t) {
            float4 v = sO[t * 32 + k4];
            acc[t] = fmaf(v.x, w0, acc[t]);
            acc[t] = fmaf(v.y, w1, acc[t]);
            acc[t] = fmaf(v.z, w2, acc[t]);
            acc[t] = fmaf(v.w, w3, acc[t]);
        }
    }
#pragma unroll
    for (int t = 0; t < 32; ++t)
        out[(size_t)(t0 + t) * CIN + j] = acc[t] * ssp[t] + x[(size_t)(t0 + t) * CIN + j];
}

// ==================== launcher ====================
extern "C" void kernel_launch(void* const* d_in, const int* in_sizes, int n_in,
                              void* d_out, int out_size) {
    const float* x  = (const float*)d_in[0];
    const float* Wt = (const float*)d_in[1];
    const float* bt = (const float*)d_in[2];
    const float* Wp = (const float*)d_in[3];
    const float* bp = (const float*)d_in[4];
    const float* Wa = (const float*)d_in[5];
    const float* ba = (const float*)d_in[6];
    const float* Wm = (const float*)d_in[7];
    const float* Wd = (const float*)d_in[8];
    const float* bd = (const float*)d_in[9];
    float* out = (float*)d_out;

    cudaFuncSetAttribute(fat_kernel, cudaFuncAttributeMaxDynamicSharedMemorySize, FLASH_SMEM);
    cudaFuncSetAttribute(proj_mma_kernel, cudaFuncAttributeMaxDynamicSharedMemorySize, PROJ_SMEM);

    convert_kernel<<<2432, 256>>>(x, Wt, Wp, Wa);                  // 1
    zero_logits_kernel<<<8, 1024>>>();                             // 2
    proj_mma_kernel<<<dim3(128, 3), 128, PROJ_SMEM>>>(bt, bp, ba); // 3
    fat_kernel<<<NFLASH + NGATE, 128, FLASH_SMEM>>>(x, Wd);        // 4
    gate_softmax<<<8, 1024>>>(bd);                                 // 5
    epilogue_kernel<<<256, 256>>>(x, Wm, out);                     // 6
}